// round 3
// baseline (speedup 1.0000x reference)
#include <cuda_runtime.h>
#include <cfloat>
#include <cstddef>

// Problem constants (fixed by the reference)
#define Bn 16
#define Tn 2048
#define Dn 256
#define Qn 4
#define Kn 1024
#define Mn (Bn*Tn)          // 32768 tokens

// GEMM tiling
#define MT 128
#define NT 128
#define KC 8

#define LOSS_SLOTS 1024

// Scratch (no cudaMalloc allowed): __device__ globals
__device__ float  g_residual[Mn*Dn];      // 32 MB running residual
__device__ float  g_quant[Mn*Dn];         // 32 MB accumulated quantization
__device__ float  g_c2[Qn*Kn];            // codeword squared norms (XLA-style)
__device__ float  g_r2[Mn];               // per-token residual squared norms
__device__ int    g_idx[Qn*Mn];           // chosen indices per stage
__device__ double g_losspart[LOSS_SLOTS]; // spread loss accumulators

// XLA-mimicking warp row-norm: separate rounded multiply + add (NO FMA),
// lane-strided ascending, then shfl_down tree 16..1.
__device__ __forceinline__ float warp_rownorm(const float* __restrict__ row, int lane) {
    float s = 0.f;
    #pragma unroll
    for (int d = lane; d < Dn; d += 32) {
        float v = row[d];
        s = __fadd_rn(s, __fmul_rn(v, v));
    }
    #pragma unroll
    for (int off = 16; off; off >>= 1)
        s = __fadd_rn(s, __shfl_down_sync(0xffffffffu, s, off));
    return s;
}

// ---------------------------------------------------------------------------
// init: residual = x (vectorized), zero loss accumulators
// ---------------------------------------------------------------------------
__global__ void init_kernel(const float4* __restrict__ x4) {
    int i = blockIdx.x * blockDim.x + threadIdx.x;   // covers Mn*Dn/4
    ((float4*)g_residual)[i] = x4[i];
    if (i < LOSS_SLOTS) g_losspart[i] = 0.0;
}

// ---------------------------------------------------------------------------
// c2: squared norm of every codeword (one warp per codeword, XLA-style)
// ---------------------------------------------------------------------------
__global__ void c2_kernel(const float* __restrict__ cbs) {
    int w    = (blockIdx.x * blockDim.x + threadIdx.x) >> 5;
    int lane = threadIdx.x & 31;
    if (w >= Qn * Kn) return;
    float s = warp_rownorm(cbs + (size_t)w * Dn, lane);
    if (lane == 0) g_c2[w] = s;
}

// ---------------------------------------------------------------------------
// r2: squared norm of every residual row (one warp per token, XLA-style)
// ---------------------------------------------------------------------------
__global__ void r2_kernel() {
    int w    = (blockIdx.x * blockDim.x + threadIdx.x) >> 5;
    int lane = threadIdx.x & 31;
    if (w >= Mn) return;
    float s = warp_rownorm(g_residual + (size_t)w * Dn, lane);
    if (lane == 0) g_r2[w] = s;
}

// ---------------------------------------------------------------------------
// Fused distance-GEMM + argmin, reference-faithful scoring:
//   d = fl( fl( r2_token - fl(2*dot) ) + c2_code )
// dot accumulated with single fp32 FFMA accumulator, k ascending (cublas-like).
// Strict lowest-index tie-break (matches jnp.argmin).
// Block: 128 tokens x all 1024 codes (128-wide tiles). 256 threads,
// 8x8 micro-tile per thread, split fragments for conflict-free LDS.128.
// ---------------------------------------------------------------------------
__global__ void __launch_bounds__(256, 2)
argmin_kernel(const float* __restrict__ cbs, int q, float* __restrict__ out_idx_f)
{
    __shared__ float As[KC][MT];
    __shared__ float Bs[KC][NT];

    const float* cb = cbs + (size_t)q * Kn * Dn;
    const float* c2 = g_c2 + q * Kn;

    int tid = threadIdx.x;
    int tx = tid & 15, ty = tid >> 4;
    int rowBase = blockIdx.x * MT;
    int ldRow = tid >> 1;            // 0..127
    int ldCol = (tid & 1) * 4;       // 0 or 4

    // my 8 rows and their t1 (= ||r||^2) values
    int   rows[8];
    float r2v[8];
    #pragma unroll
    for (int i = 0; i < 8; i++) {
        rows[i] = rowBase + ((i < 4) ? ty * 4 + i : 64 + ty * 4 + (i - 4));
        r2v[i]  = g_r2[rows[i]];
    }

    float bestV[8]; int bestI[8];
    #pragma unroll
    for (int i = 0; i < 8; i++) { bestV[i] = FLT_MAX; bestI[i] = 0x7fffffff; }

    for (int n0 = 0; n0 < Kn; n0 += NT) {
        float acc[8][8];
        #pragma unroll
        for (int i = 0; i < 8; i++)
            #pragma unroll
            for (int j = 0; j < 8; j++) acc[i][j] = 0.f;

        for (int d0 = 0; d0 < Dn; d0 += KC) {
            float4 a = *(const float4*)(g_residual + (size_t)(rowBase + ldRow) * Dn + d0 + ldCol);
            float4 b = *(const float4*)(cb         + (size_t)(n0      + ldRow) * Dn + d0 + ldCol);
            __syncthreads();   // previous tile's shared reads done
            As[ldCol+0][ldRow] = a.x; As[ldCol+1][ldRow] = a.y;
            As[ldCol+2][ldRow] = a.z; As[ldCol+3][ldRow] = a.w;
            Bs[ldCol+0][ldRow] = b.x; Bs[ldCol+1][ldRow] = b.y;
            Bs[ldCol+2][ldRow] = b.z; Bs[ldCol+3][ldRow] = b.w;
            __syncthreads();

            #pragma unroll
            for (int kk = 0; kk < KC; kk++) {
                float4 a0 = *(const float4*)&As[kk][ty * 4];
                float4 a1 = *(const float4*)&As[kk][64 + ty * 4];
                float4 b0 = *(const float4*)&Bs[kk][tx * 4];
                float4 b1 = *(const float4*)&Bs[kk][64 + tx * 4];
                float af[8] = {a0.x,a0.y,a0.z,a0.w,a1.x,a1.y,a1.z,a1.w};
                float bf[8] = {b0.x,b0.y,b0.z,b0.w,b1.x,b1.y,b1.z,b1.w};
                #pragma unroll
                for (int i = 0; i < 8; i++)
                    #pragma unroll
                    for (int j = 0; j < 8; j++)
                        acc[i][j] += af[i] * bf[j];   // FFMA, k ascending
            }
        }

        // fold this 128-wide code tile with reference-faithful rounding
        #pragma unroll
        for (int j = 0; j < 8; j++) {
            int col = n0 + ((j < 4) ? tx * 4 + j : 64 + tx * 4 + (j - 4));
            float cc = c2[col];
            #pragma unroll
            for (int i = 0; i < 8; i++) {
                float t  = __fsub_rn(r2v[i], __fmul_rn(2.0f, acc[i][j]));
                float s  = __fadd_rn(t, cc);
                if (s < bestV[i] || (s == bestV[i] && col < bestI[i])) {
                    bestV[i] = s; bestI[i] = col;
                }
            }
        }
    }

    // reduce across the 16 column-threads (tx), lowest index on value ties
    #pragma unroll
    for (int i = 0; i < 8; i++) {
        float v = bestV[i]; int id = bestI[i];
        #pragma unroll
        for (int off = 8; off >= 1; off >>= 1) {
            float v2 = __shfl_down_sync(0xffffffffu, v, off, 16);
            int   i2 = __shfl_down_sync(0xffffffffu, id, off, 16);
            if (v2 < v || (v2 == v && i2 < id)) { v = v2; id = i2; }
        }
        if (tx == 0) {
            g_idx[q * Mn + rows[i]] = id;
            out_idx_f[(size_t)q * Mn + rows[i]] = (float)id;  // indices as f32
        }
    }
}

// ---------------------------------------------------------------------------
// Gather + residual/quant update + loss accumulation. One block per token.
// Replicates reference rounding: quant = ((qv0+qv1)+qv2)+qv3 (fp32 adds),
// residual chain r -= qv, and on last stage out = x + (quant - x).
// ---------------------------------------------------------------------------
__global__ void update_kernel(const float* __restrict__ cbs, int q,
                              const float* __restrict__ x,
                              float* __restrict__ out_quant, int is_last)
{
    int token = blockIdx.x;
    int d = threadIdx.x;
    int k = g_idx[q * Mn + token];
    const float* cbrow = cbs + ((size_t)q * Kn + k) * Dn;
    size_t off = (size_t)token * Dn + d;
    float qv = cbrow[d];
    float r  = __fsub_rn(g_residual[off], qv);
    g_residual[off] = r;
    float quant = (q == 0) ? qv : __fadd_rn(g_quant[off], qv);
    g_quant[off] = quant;
    if (is_last) out_quant[off] = __fadd_rn(x[off], __fsub_rn(quant, x[off]));

    __shared__ float red[256];
    red[d] = r * r;
    __syncthreads();
    #pragma unroll
    for (int s = 128; s > 0; s >>= 1) {
        if (d < s) red[d] += red[d + s];
        __syncthreads();
    }
    if (d == 0) atomicAdd(&g_losspart[token & (LOSS_SLOTS - 1)], (double)red[0]);
}

// ---------------------------------------------------------------------------
// finalize: vq_loss = 1.25 * sum(r_new^2 over all stages) / (M*D)
// (codebook_loss == commit_loss numerically; all Q returned losses equal)
// ---------------------------------------------------------------------------
__global__ void finalize_kernel(float* __restrict__ out_loss)
{
    __shared__ double red[256];
    double s = 0.0;
    for (int i = threadIdx.x; i < LOSS_SLOTS; i += 256) s += g_losspart[i];
    red[threadIdx.x] = s;
    __syncthreads();
    #pragma unroll
    for (int st = 128; st > 0; st >>= 1) {
        if (threadIdx.x < st) red[threadIdx.x] += red[threadIdx.x + st];
        __syncthreads();
    }
    if (threadIdx.x == 0) {
        float v = (float)(1.25 * red[0] / (double)((size_t)Mn * Dn));
        #pragma unroll
        for (int q = 0; q < Qn; q++) out_loss[q] = v;
    }
}

// ---------------------------------------------------------------------------
extern "C" void kernel_launch(void* const* d_in, const int* in_sizes, int n_in,
                              void* d_out, int out_size)
{
    const float* x   = (const float*)d_in[0];
    const float* cbs = (const float*)d_in[1];
    // defensive: detect swapped input order via element counts
    if (n_in >= 2 && in_sizes[0] == Qn * Kn * Dn && in_sizes[1] == Mn * Dn) {
        const float* t = x; x = cbs; cbs = t;
    }

    float* out       = (float*)d_out;
    float* out_quant = out;                              // [B,T,D]
    float* out_idx   = out + (size_t)Mn * Dn;            // [Q,B,T] as f32
    float* out_loss  = out + (size_t)Mn * Dn + (size_t)Qn * Mn;  // 4 scalars
    (void)out_size;

    init_kernel<<<(Mn * Dn / 4) / 256, 256>>>((const float4*)x);
    c2_kernel<<<(Qn * Kn * 32) / 256, 256>>>(cbs);

    for (int q = 0; q < Qn; q++) {
        r2_kernel<<<(Mn * 32) / 256, 256>>>();          // t1 for this stage
        argmin_kernel<<<Mn / MT, 256>>>(cbs, q, out_idx);
        update_kernel<<<Mn, 256>>>(cbs, q, x, out_quant, (q == Qn - 1) ? 1 : 0);
    }

    finalize_kernel<<<1, 256>>>(out_loss);
}

// round 5
// speedup vs baseline: 2.5740x; 2.5740x over previous
#include <cuda_runtime.h>
#include <cuda_bf16.h>
#include <cfloat>
#include <cstddef>
#include <cstdint>

// Problem constants (fixed by the reference)
#define Bn 16
#define Tn 2048
#define Dn 256
#define Qn 4
#define Kn 1024
#define Mn (Bn*Tn)          // 32768 tokens

#define LOSS_SLOTS 1024
#define WWIN  3.0f           // candidate window >= 2x worst-case bf16 score error
#define CANDCAP 32

// ------------------------- device global scratch ---------------------------
__device__ __align__(16) float          g_residual[Mn*Dn];
__device__ __align__(16) float          g_quant[Mn*Dn];
__device__ __align__(16) float          g_c2[Qn*Kn];
__device__ __align__(16) float          g_r2[Mn];
__device__              int             g_idx[Qn*Mn];
__device__              double          g_losspart[LOSS_SLOTS];
__device__ __align__(16) __nv_bfloat16  g_Apack[(size_t)Mn*Dn];      // bf16(residual)
__device__ __align__(16) __nv_bfloat16  g_Bpack[(size_t)Qn*Kn*Dn];   // bf16(codebooks)
__device__ __align__(16) float          g_scores[(size_t)Mn*Kn];     // 128 MB approx scores

// ------------------------------ PTX helpers --------------------------------
__device__ __forceinline__ uint32_t smem_to_u32(const void* p) {
    uint32_t a;
    asm("{ .reg .u64 t; cvta.to.shared.u64 t, %1; cvt.u32.u64 %0, t; }"
        : "=r"(a) : "l"(p));
    return a;
}
#define CP_ASYNC16(dst, src) \
    asm volatile("cp.async.cg.shared.global [%0], [%1], 16;" :: "r"(dst), "l"(src))
#define CP_COMMIT() asm volatile("cp.async.commit_group;" ::: "memory")
#define CP_WAIT0()  asm volatile("cp.async.wait_group 0;" ::: "memory")
#define LDSM_X4(r0, r1, r2, r3, addr) \
    asm volatile("ldmatrix.sync.aligned.m8n8.x4.shared.b16 {%0,%1,%2,%3}, [%4];" \
                 : "=r"(r0), "=r"(r1), "=r"(r2), "=r"(r3) : "r"(addr))
#define MMA16816(c, a, b0v, b1v) \
    asm volatile("mma.sync.aligned.m16n8k16.row.col.f32.bf16.bf16.f32 " \
                 "{%0,%1,%2,%3}, {%4,%5,%6,%7}, {%8,%9}, {%0,%1,%2,%3};" \
                 : "+f"((c)[0]), "+f"((c)[1]), "+f"((c)[2]), "+f"((c)[3]) \
                 : "r"((a)[0]), "r"((a)[1]), "r"((a)[2]), "r"((a)[3]), \
                   "r"(b0v), "r"(b1v))

// XLA-mimicking warp row-norm: separate rounded multiply + add (NO FMA),
// lane-strided ascending, then shfl_down tree 16..1.  (bit-exact, round 3)
__device__ __forceinline__ float warp_rownorm(const float* __restrict__ row, int lane) {
    float s = 0.f;
    #pragma unroll
    for (int d = lane; d < Dn; d += 32) {
        float v = row[d];
        s = __fadd_rn(s, __fmul_rn(v, v));
    }
    #pragma unroll
    for (int off = 16; off; off >>= 1)
        s = __fadd_rn(s, __shfl_down_sync(0xffffffffu, s, off));
    return s;
}

// ---------------------------------------------------------------------------
__global__ void init_kernel(const float4* __restrict__ x4) {
    int i = blockIdx.x * blockDim.x + threadIdx.x;
    ((float4*)g_residual)[i] = x4[i];
    if (i < LOSS_SLOTS) g_losspart[i] = 0.0;
}

__global__ void c2_kernel(const float* __restrict__ cbs) {
    int w    = (blockIdx.x * blockDim.x + threadIdx.x) >> 5;
    int lane = threadIdx.x & 31;
    if (w >= Qn * Kn) return;
    float s = warp_rownorm(cbs + (size_t)w * Dn, lane);
    if (lane == 0) g_c2[w] = s;
}

__global__ void r2_kernel() {
    int w    = (blockIdx.x * blockDim.x + threadIdx.x) >> 5;
    int lane = threadIdx.x & 31;
    if (w >= Mn) return;
    float s = warp_rownorm(g_residual + (size_t)w * Dn, lane);
    if (lane == 0) g_r2[w] = s;
}

// residual -> bf16 (4 elems/thread, vectorized)
__global__ void packA_kernel() {
    int i = (blockIdx.x * blockDim.x + threadIdx.x) * 4;
    float4 v = *(const float4*)(g_residual + i);
    __nv_bfloat162* dst = (__nv_bfloat162*)(g_Apack + i);
    dst[0] = __floats2bfloat162_rn(v.x, v.y);
    dst[1] = __floats2bfloat162_rn(v.z, v.w);
}

// codebooks -> bf16 (once)
__global__ void packB_kernel(const float* __restrict__ cbs) {
    int i = (blockIdx.x * blockDim.x + threadIdx.x) * 4;
    float4 v = *(const float4*)(cbs + i);
    __nv_bfloat162* dst = (__nv_bfloat162*)(g_Bpack + i);
    dst[0] = __floats2bfloat162_rn(v.x, v.y);
    dst[1] = __floats2bfloat162_rn(v.z, v.w);
}

// ---------------------------------------------------------------------------
// bf16 HMMA GEMM: 128 tokens/CTA x 1024 codes, K=256 in 4 chunks of 64.
// Writes approx scores s = fl(fl(r2 - 2*dot) + c2) to g_scores.
// SMEM: A/B chunk buffers [128 rows x 64 bf16] double-buffered, 16B-chunk
// XOR swizzle (chunk ^= row&7) for conflict-free ldmatrix + cp.async stores.
// Warps: 4(m) x 2(n); warp tile 32x64; mma m16n8k16.
// ---------------------------------------------------------------------------
#define SM_A0 0
#define SM_A1 16384
#define SM_B0 32768
#define SM_B1 49152
#define SM_C2 65536
#define SM_TOT (65536 + 4096)

__global__ void __launch_bounds__(256, 2)
gemm_kernel(int q)
{
    extern __shared__ char smem[];
    uint32_t sb = smem_to_u32(smem);
    float* c2s = (float*)(smem + SM_C2);

    int tid = threadIdx.x, lane = tid & 31, wid = tid >> 5;
    int wm = wid >> 1, wn = wid & 1;
    int rowBase = blockIdx.x * 128;

    for (int i = tid; i < Kn; i += 256) c2s[i] = g_c2[q * Kn + i];

    // r2 of my 4 output rows
    float r2a[2][2];
    #pragma unroll
    for (int mf = 0; mf < 2; mf++)
        #pragma unroll
        for (int h = 0; h < 2; h++)
            r2a[mf][h] = g_r2[rowBase + wm * 32 + mf * 16 + (lane >> 2) + h * 8];

    // loader indices (8 cp.async per thread per chunk)
    int ldrow = tid >> 1;                 // covers 128 rows with 2 threads each
    // each thread loads 4 x 16B for A and 4 x 16B for B per chunk:
    // idx j in 0..3: linear = tid + 256*j -> row = linear>>3, m8 = linear&7
    __syncthreads();

    const __nv_bfloat16* baseB = g_Bpack + (size_t)q * Kn * Dn;
    (void)ldrow;

    for (int nt = 0; nt < 8; nt++) {
        float acc[2][8][4];
        #pragma unroll
        for (int a = 0; a < 2; a++)
            #pragma unroll
            for (int b = 0; b < 8; b++)
                #pragma unroll
                for (int c = 0; c < 4; c++) acc[a][b][c] = 0.f;

        // ---- preload chunk 0 ----
        {
            #pragma unroll
            for (int j = 0; j < 4; j++) {
                int linear = tid + 256 * j;
                int row = linear >> 3, m8 = linear & 7;
                uint32_t sw = (uint32_t)((m8 ^ (row & 7)) << 4);
                CP_ASYNC16(sb + SM_A0 + row * 128 + sw,
                           g_Apack + (size_t)(rowBase + row) * Dn + m8 * 8);
                CP_ASYNC16(sb + SM_B0 + row * 128 + sw,
                           baseB + (size_t)(nt * 128 + row) * Dn + m8 * 8);
            }
            CP_COMMIT(); CP_WAIT0();
        }
        __syncthreads();

        for (int cc = 0; cc < 4; cc++) {
            if (cc < 3) {     // issue next chunk into other buffer
                uint32_t abuf = ((cc + 1) & 1) ? SM_A1 : SM_A0;
                uint32_t bbuf = ((cc + 1) & 1) ? SM_B1 : SM_B0;
                int koff = (cc + 1) * 64;
                #pragma unroll
                for (int j = 0; j < 4; j++) {
                    int linear = tid + 256 * j;
                    int row = linear >> 3, m8 = linear & 7;
                    uint32_t sw = (uint32_t)((m8 ^ (row & 7)) << 4);
                    CP_ASYNC16(sb + abuf + row * 128 + sw,
                               g_Apack + (size_t)(rowBase + row) * Dn + koff + m8 * 8);
                    CP_ASYNC16(sb + bbuf + row * 128 + sw,
                               baseB + (size_t)(nt * 128 + row) * Dn + koff + m8 * 8);
                }
                CP_COMMIT();
            }
            uint32_t abase = sb + ((cc & 1) ? SM_A1 : SM_A0);
            uint32_t bbase = sb + ((cc & 1) ? SM_B1 : SM_B0);

            #pragma unroll
            for (int ks = 0; ks < 4; ks++) {
                uint32_t afr[2][4];
                #pragma unroll
                for (int mf = 0; mf < 2; mf++) {
                    int t = lane >> 3;
                    int row = wm * 32 + mf * 16 + (lane & 7) + ((t & 1) << 3);
                    int kk  = ks * 16 + ((t >> 1) << 3);
                    uint32_t addr = abase + row * 128 + ((((kk >> 3) ^ (row & 7)) << 4));
                    LDSM_X4(afr[mf][0], afr[mf][1], afr[mf][2], afr[mf][3], addr);
                }
                #pragma unroll
                for (int nf2 = 0; nf2 < 4; nf2++) {
                    uint32_t b0, b1, b2, b3;
                    int t = lane >> 3;
                    int row = wn * 64 + nf2 * 16 + ((t >> 1) << 3) + (lane & 7);
                    int kk  = ks * 16 + ((t & 1) << 3);
                    uint32_t addr = bbase + row * 128 + ((((kk >> 3) ^ (row & 7)) << 4));
                    LDSM_X4(b0, b1, b2, b3, addr);
                    MMA16816(acc[0][nf2 * 2],     afr[0], b0, b1);
                    MMA16816(acc[0][nf2 * 2 + 1], afr[0], b2, b3);
                    MMA16816(acc[1][nf2 * 2],     afr[1], b0, b1);
                    MMA16816(acc[1][nf2 * 2 + 1], afr[1], b2, b3);
                }
            }
            if (cc < 3) CP_WAIT0();
            __syncthreads();
        }

        // ---- epilogue: approx scores to global ----
        #pragma unroll
        for (int mf = 0; mf < 2; mf++) {
            int ra = rowBase + wm * 32 + mf * 16 + (lane >> 2);
            #pragma unroll
            for (int nf = 0; nf < 8; nf++) {
                int col = nt * 128 + wn * 64 + nf * 8 + (lane & 3) * 2;
                float cA = c2s[col], cB = c2s[col + 1];
                float2 s0, s1;
                s0.x = __fadd_rn(__fsub_rn(r2a[mf][0], __fmul_rn(2.f, acc[mf][nf][0])), cA);
                s0.y = __fadd_rn(__fsub_rn(r2a[mf][0], __fmul_rn(2.f, acc[mf][nf][1])), cB);
                s1.x = __fadd_rn(__fsub_rn(r2a[mf][1], __fmul_rn(2.f, acc[mf][nf][2])), cA);
                s1.y = __fadd_rn(__fsub_rn(r2a[mf][1], __fmul_rn(2.f, acc[mf][nf][3])), cB);
                *(float2*)(g_scores + (size_t)ra * Kn + col)       = s0;
                *(float2*)(g_scores + (size_t)(ra + 8) * Kn + col) = s1;
            }
        }
        __syncthreads();
    }
}

// ---------------------------------------------------------------------------
// Scan: per token, find approx min, candidates within WWIN, exact-evaluate
// candidates with the reference-faithful chain (round-3 bit-exact arithmetic).
// One warp per token, 8 tokens per block.
// ---------------------------------------------------------------------------
__global__ void scan_kernel(const float* __restrict__ cbs, int q,
                            float* __restrict__ out_idx_f)
{
    int wid = threadIdx.x >> 5, lane = threadIdx.x & 31;
    int token = blockIdx.x * 8 + wid;
    const float4* sc4 = (const float4*)(g_scores + (size_t)token * Kn);
    const float* cb = cbs + (size_t)q * Kn * Dn;

    float4 v[8];
    float mn = FLT_MAX;
    #pragma unroll
    for (int i = 0; i < 8; i++) {
        v[i] = sc4[i * 32 + lane];
        mn = fminf(mn, fminf(fminf(v[i].x, v[i].y), fminf(v[i].z, v[i].w)));
    }
    #pragma unroll
    for (int off = 16; off; off >>= 1)
        mn = fminf(mn, __shfl_xor_sync(0xffffffffu, mn, off));
    float thr = mn + WWIN;

    __shared__ int cnts[8];
    __shared__ int lists[8][CANDCAP];
    if (lane == 0) cnts[wid] = 0;
    __syncwarp();
    #pragma unroll
    for (int i = 0; i < 8; i++) {
        int base = (i * 32 + lane) * 4;
        float sv[4] = {v[i].x, v[i].y, v[i].z, v[i].w};
        #pragma unroll
        for (int c = 0; c < 4; c++) {
            if (sv[c] <= thr) {
                int p = atomicAdd(&cnts[wid], 1);
                if (p < CANDCAP) lists[wid][p] = base + c;
            }
        }
    }
    __syncwarp();
    int cnt = cnts[wid];
    int winner;

    if (cnt == 1) {
        winner = lists[wid][0];
    } else {
        const float* rrow = g_residual + (size_t)token * Dn;
        float r2 = g_r2[token];
        float bv = FLT_MAX; int bi = 0x7fffffff;
        if (cnt <= CANDCAP) {
            if (lane < cnt) {
                int k = lists[wid][lane];
                const float* cr = cb + (size_t)k * Dn;
                float acc = 0.f;
                #pragma unroll 8
                for (int d = 0; d < Dn; d++) acc = __fmaf_rn(rrow[d], cr[d], acc);
                bv = __fadd_rn(__fsub_rn(r2, __fmul_rn(2.f, acc)), g_c2[q * Kn + k]);
                bi = k;
            }
        } else {
            // overflow fallback: full exact scan (essentially never taken)
            for (int k = lane; k < Kn; k += 32) {
                const float* cr = cb + (size_t)k * Dn;
                float acc = 0.f;
                #pragma unroll 8
                for (int d = 0; d < Dn; d++) acc = __fmaf_rn(rrow[d], cr[d], acc);
                float s = __fadd_rn(__fsub_rn(r2, __fmul_rn(2.f, acc)), g_c2[q * Kn + k]);
                if (s < bv || (s == bv && k < bi)) { bv = s; bi = k; }
            }
        }
        #pragma unroll
        for (int off = 16; off; off >>= 1) {
            float ov = __shfl_xor_sync(0xffffffffu, bv, off);
            int   oi = __shfl_xor_sync(0xffffffffu, bi, off);
            if (ov < bv || (ov == bv && oi < bi)) { bv = ov; bi = oi; }
        }
        winner = bi;
    }

    if (lane == 0) {
        g_idx[q * Mn + token] = winner;
        out_idx_f[(size_t)q * Mn + token] = (float)winner;
    }
}

// ---------------------------------------------------------------------------
// Gather + residual/quant update + loss accumulation (bit-exact, round 3).
// ---------------------------------------------------------------------------
__global__ void update_kernel(const float* __restrict__ cbs, int q,
                              const float* __restrict__ x,
                              float* __restrict__ out_quant, int is_last)
{
    int token = blockIdx.x;
    int d = threadIdx.x;
    int k = g_idx[q * Mn + token];
    const float* cbrow = cbs + ((size_t)q * Kn + k) * Dn;
    size_t off = (size_t)token * Dn + d;
    float qv = cbrow[d];
    float r  = __fsub_rn(g_residual[off], qv);
    g_residual[off] = r;
    float quant = (q == 0) ? qv : __fadd_rn(g_quant[off], qv);
    g_quant[off] = quant;
    if (is_last) out_quant[off] = __fadd_rn(x[off], __fsub_rn(quant, x[off]));

    __shared__ float red[256];
    red[d] = r * r;
    __syncthreads();
    #pragma unroll
    for (int s = 128; s > 0; s >>= 1) {
        if (d < s) red[d] += red[d + s];
        __syncthreads();
    }
    if (d == 0) atomicAdd(&g_losspart[token & (LOSS_SLOTS - 1)], (double)red[0]);
}

__global__ void finalize_kernel(float* __restrict__ out_loss)
{
    __shared__ double red[256];
    double s = 0.0;
    for (int i = threadIdx.x; i < LOSS_SLOTS; i += 256) s += g_losspart[i];
    red[threadIdx.x] = s;
    __syncthreads();
    #pragma unroll
    for (int st = 128; st > 0; st >>= 1) {
        if (threadIdx.x < st) red[threadIdx.x] += red[threadIdx.x + st];
        __syncthreads();
    }
    if (threadIdx.x == 0) {
        float v = (float)(1.25 * red[0] / (double)((size_t)Mn * Dn));
        #pragma unroll
        for (int q = 0; q < Qn; q++) out_loss[q] = v;
    }
}

// ---------------------------------------------------------------------------
extern "C" void kernel_launch(void* const* d_in, const int* in_sizes, int n_in,
                              void* d_out, int out_size)
{
    const float* x   = (const float*)d_in[0];
    const float* cbs = (const float*)d_in[1];
    if (n_in >= 2 && in_sizes[0] == Qn * Kn * Dn && in_sizes[1] == Mn * Dn) {
        const float* t = x; x = cbs; cbs = t;
    }

    float* out       = (float*)d_out;
    float* out_quant = out;                                       // [B,T,D]
    float* out_idx   = out + (size_t)Mn * Dn;                     // [Q,B,T]
    float* out_loss  = out + (size_t)Mn * Dn + (size_t)Qn * Mn;   // 4 scalars
    (void)out_size;

    cudaFuncSetAttribute(gemm_kernel,
                         cudaFuncAttributeMaxDynamicSharedMemorySize, SM_TOT);

    init_kernel<<<(Mn * Dn / 4) / 256, 256>>>((const float4*)x);
    c2_kernel<<<(Qn * Kn * 32) / 256, 256>>>(cbs);
    packB_kernel<<<(Qn * Kn * Dn / 4) / 256, 256>>>(cbs);

    for (int q = 0; q < Qn; q++) {
        packA_kernel<<<(Mn * Dn / 4) / 256, 256>>>();
        r2_kernel<<<(Mn * 32) / 256, 256>>>();
        gemm_kernel<<<Mn / 128, 256, SM_TOT>>>(q);
        scan_kernel<<<Mn / 8, 256>>>(cbs, q, out_idx);
        update_kernel<<<Mn, 256>>>(cbs, q, x, out_quant, (q == Qn - 1) ? 1 : 0);
    }

    finalize_kernel<<<1, 256>>>(out_loss);
}

// round 6
// speedup vs baseline: 2.9795x; 1.1575x over previous
#include <cuda_runtime.h>
#include <cuda_bf16.h>
#include <cuda_fp16.h>
#include <cfloat>
#include <cstddef>
#include <cstdint>

// Problem constants (fixed by the reference)
#define Bn 16
#define Tn 2048
#define Dn 256
#define Qn 4
#define Kn 1024
#define Mn (Bn*Tn)          // 32768 tokens

#define LOSS_SLOTS 1024
#define WWIN  4.0f           // candidate window: 2x(bf16 gemm err) + fp16 ulp slack
#define CANDCAP 32

// ------------------------- device global scratch ---------------------------
__device__ __align__(16) float          g_residual[Mn*Dn];
__device__ __align__(16) float          g_quant[Mn*Dn];
__device__ __align__(16) float          g_c2[Qn*Kn];
__device__ __align__(16) float          g_r2[Mn];
__device__              double          g_losspart[LOSS_SLOTS];
__device__ __align__(16) __nv_bfloat16  g_Apack[(size_t)Mn*Dn];      // bf16(residual)
__device__ __align__(16) __nv_bfloat16  g_Bpack[(size_t)Qn*Kn*Dn];   // bf16(codebooks)
__device__ __align__(16) __half         g_scores[(size_t)Mn*Kn];     // 64 MB approx scores

// ------------------------------ PTX helpers --------------------------------
__device__ __forceinline__ uint32_t smem_to_u32(const void* p) {
    uint32_t a;
    asm("{ .reg .u64 t; cvta.to.shared.u64 t, %1; cvt.u32.u64 %0, t; }"
        : "=r"(a) : "l"(p));
    return a;
}
#define CP_ASYNC16(dst, src) \
    asm volatile("cp.async.cg.shared.global [%0], [%1], 16;" :: "r"(dst), "l"(src))
#define CP_COMMIT() asm volatile("cp.async.commit_group;" ::: "memory")
#define CP_WAIT0()  asm volatile("cp.async.wait_group 0;" ::: "memory")
#define LDSM_X4(r0, r1, r2, r3, addr) \
    asm volatile("ldmatrix.sync.aligned.m8n8.x4.shared.b16 {%0,%1,%2,%3}, [%4];" \
                 : "=r"(r0), "=r"(r1), "=r"(r2), "=r"(r3) : "r"(addr))
#define MMA16816(c, a, b0v, b1v) \
    asm volatile("mma.sync.aligned.m16n8k16.row.col.f32.bf16.bf16.f32 " \
                 "{%0,%1,%2,%3}, {%4,%5,%6,%7}, {%8,%9}, {%0,%1,%2,%3};" \
                 : "+f"((c)[0]), "+f"((c)[1]), "+f"((c)[2]), "+f"((c)[3]) \
                 : "r"((a)[0]), "r"((a)[1]), "r"((a)[2]), "r"((a)[3]), \
                   "r"(b0v), "r"(b1v))

// XLA-mimicking warp row-norm: separate rounded multiply + add (NO FMA),
// lane-strided ascending, then shfl_down tree 16..1.  (bit-exact, round 3)
__device__ __forceinline__ float warp_rownorm(const float* __restrict__ row, int lane) {
    float s = 0.f;
    #pragma unroll
    for (int d = lane; d < Dn; d += 32) {
        float v = row[d];
        s = __fadd_rn(s, __fmul_rn(v, v));
    }
    #pragma unroll
    for (int off = 16; off; off >>= 1)
        s = __fadd_rn(s, __shfl_down_sync(0xffffffffu, s, off));
    return s;
}

// ---------------------------------------------------------------------------
// prep0: residual = x, bf16 pack, r2 (XLA-exact order), zero loss slots.
// One warp per token, 8 warps per block.
// ---------------------------------------------------------------------------
__global__ void prep0_kernel(const float* __restrict__ x) {
    int wid = threadIdx.x >> 5, lane = threadIdx.x & 31;
    int token = blockIdx.x * 8 + wid;
    size_t base = (size_t)token * Dn;
    float s = 0.f;
    #pragma unroll
    for (int j = 0; j < 8; j++) {
        int d = lane + 32 * j;
        float v = x[base + d];
        g_residual[base + d] = v;
        g_Apack[base + d] = __float2bfloat16_rn(v);
        s = __fadd_rn(s, __fmul_rn(v, v));
    }
    #pragma unroll
    for (int off = 16; off; off >>= 1)
        s = __fadd_rn(s, __shfl_down_sync(0xffffffffu, s, off));
    if (lane == 0) g_r2[token] = s;
    if (blockIdx.x == 0) {
        for (int i = threadIdx.x; i < LOSS_SLOTS; i += 256) g_losspart[i] = 0.0;
    }
}

__global__ void c2_kernel(const float* __restrict__ cbs) {
    int w    = (blockIdx.x * blockDim.x + threadIdx.x) >> 5;
    int lane = threadIdx.x & 31;
    if (w >= Qn * Kn) return;
    float s = warp_rownorm(cbs + (size_t)w * Dn, lane);
    if (lane == 0) g_c2[w] = s;
}

// codebooks -> bf16 (once)
__global__ void packB_kernel(const float* __restrict__ cbs) {
    int i = (blockIdx.x * blockDim.x + threadIdx.x) * 4;
    float4 v = *(const float4*)(cbs + i);
    __nv_bfloat162* dst = (__nv_bfloat162*)(g_Bpack + i);
    dst[0] = __floats2bfloat162_rn(v.x, v.y);
    dst[1] = __floats2bfloat162_rn(v.z, v.w);
}

// ---------------------------------------------------------------------------
// bf16 HMMA GEMM: 128 tokens/CTA x 1024 codes, K=256 in 4 chunks of 64.
// Writes approx scores s = fl(fl(r2 - 2*dot) + c2) as fp16 to g_scores.
// ---------------------------------------------------------------------------
#define SM_A0 0
#define SM_A1 16384
#define SM_B0 32768
#define SM_B1 49152
#define SM_C2 65536
#define SM_TOT (65536 + 4096)

__global__ void __launch_bounds__(256, 2)
gemm_kernel(int q)
{
    extern __shared__ char smem[];
    uint32_t sb = smem_to_u32(smem);
    float* c2s = (float*)(smem + SM_C2);

    int tid = threadIdx.x, lane = tid & 31, wid = tid >> 5;
    int wm = wid >> 1, wn = wid & 1;
    int rowBase = blockIdx.x * 128;

    for (int i = tid; i < Kn; i += 256) c2s[i] = g_c2[q * Kn + i];

    float r2a[2][2];
    #pragma unroll
    for (int mf = 0; mf < 2; mf++)
        #pragma unroll
        for (int h = 0; h < 2; h++)
            r2a[mf][h] = g_r2[rowBase + wm * 32 + mf * 16 + (lane >> 2) + h * 8];

    __syncthreads();

    const __nv_bfloat16* baseB = g_Bpack + (size_t)q * Kn * Dn;

    for (int nt = 0; nt < 8; nt++) {
        float acc[2][8][4];
        #pragma unroll
        for (int a = 0; a < 2; a++)
            #pragma unroll
            for (int b = 0; b < 8; b++)
                #pragma unroll
                for (int c = 0; c < 4; c++) acc[a][b][c] = 0.f;

        {
            #pragma unroll
            for (int j = 0; j < 4; j++) {
                int linear = tid + 256 * j;
                int row = linear >> 3, m8 = linear & 7;
                uint32_t sw = (uint32_t)((m8 ^ (row & 7)) << 4);
                CP_ASYNC16(sb + SM_A0 + row * 128 + sw,
                           g_Apack + (size_t)(rowBase + row) * Dn + m8 * 8);
                CP_ASYNC16(sb + SM_B0 + row * 128 + sw,
                           baseB + (size_t)(nt * 128 + row) * Dn + m8 * 8);
            }
            CP_COMMIT(); CP_WAIT0();
        }
        __syncthreads();

        for (int cc = 0; cc < 4; cc++) {
            if (cc < 3) {
                uint32_t abuf = ((cc + 1) & 1) ? SM_A1 : SM_A0;
                uint32_t bbuf = ((cc + 1) & 1) ? SM_B1 : SM_B0;
                int koff = (cc + 1) * 64;
                #pragma unroll
                for (int j = 0; j < 4; j++) {
                    int linear = tid + 256 * j;
                    int row = linear >> 3, m8 = linear & 7;
                    uint32_t sw = (uint32_t)((m8 ^ (row & 7)) << 4);
                    CP_ASYNC16(sb + abuf + row * 128 + sw,
                               g_Apack + (size_t)(rowBase + row) * Dn + koff + m8 * 8);
                    CP_ASYNC16(sb + bbuf + row * 128 + sw,
                               baseB + (size_t)(nt * 128 + row) * Dn + koff + m8 * 8);
                }
                CP_COMMIT();
            }
            uint32_t abase = sb + ((cc & 1) ? SM_A1 : SM_A0);
            uint32_t bbase = sb + ((cc & 1) ? SM_B1 : SM_B0);

            #pragma unroll
            for (int ks = 0; ks < 4; ks++) {
                uint32_t afr[2][4];
                #pragma unroll
                for (int mf = 0; mf < 2; mf++) {
                    int t = lane >> 3;
                    int row = wm * 32 + mf * 16 + (lane & 7) + ((t & 1) << 3);
                    int kk  = ks * 16 + ((t >> 1) << 3);
                    uint32_t addr = abase + row * 128 + ((((kk >> 3) ^ (row & 7)) << 4));
                    LDSM_X4(afr[mf][0], afr[mf][1], afr[mf][2], afr[mf][3], addr);
                }
                #pragma unroll
                for (int nf2 = 0; nf2 < 4; nf2++) {
                    uint32_t b0, b1, b2, b3;
                    int t = lane >> 3;
                    int row = wn * 64 + nf2 * 16 + ((t >> 1) << 3) + (lane & 7);
                    int kk  = ks * 16 + ((t & 1) << 3);
                    uint32_t addr = bbase + row * 128 + ((((kk >> 3) ^ (row & 7)) << 4));
                    LDSM_X4(b0, b1, b2, b3, addr);
                    MMA16816(acc[0][nf2 * 2],     afr[0], b0, b1);
                    MMA16816(acc[0][nf2 * 2 + 1], afr[0], b2, b3);
                    MMA16816(acc[1][nf2 * 2],     afr[1], b0, b1);
                    MMA16816(acc[1][nf2 * 2 + 1], afr[1], b2, b3);
                }
            }
            if (cc < 3) CP_WAIT0();
            __syncthreads();
        }

        // ---- epilogue: fp16 approx scores to global ----
        #pragma unroll
        for (int mf = 0; mf < 2; mf++) {
            int ra = rowBase + wm * 32 + mf * 16 + (lane >> 2);
            #pragma unroll
            for (int nf = 0; nf < 8; nf++) {
                int col = nt * 128 + wn * 64 + nf * 8 + (lane & 3) * 2;
                float cA = c2s[col], cB = c2s[col + 1];
                float s0x = __fadd_rn(__fsub_rn(r2a[mf][0], __fmul_rn(2.f, acc[mf][nf][0])), cA);
                float s0y = __fadd_rn(__fsub_rn(r2a[mf][0], __fmul_rn(2.f, acc[mf][nf][1])), cB);
                float s1x = __fadd_rn(__fsub_rn(r2a[mf][1], __fmul_rn(2.f, acc[mf][nf][2])), cA);
                float s1y = __fadd_rn(__fsub_rn(r2a[mf][1], __fmul_rn(2.f, acc[mf][nf][3])), cB);
                *(__half2*)(g_scores + (size_t)ra * Kn + col)       = __floats2half2_rn(s0x, s0y);
                *(__half2*)(g_scores + (size_t)(ra + 8) * Kn + col) = __floats2half2_rn(s1x, s1y);
            }
        }
        __syncthreads();
    }
}

// ---------------------------------------------------------------------------
// Fused scan + update. One warp per token, 8 tokens per block.
// Scan: approx min over fp16 scores, candidates within WWIN, exact-evaluate
// with the reference-faithful chain (round-3 bit-exact).
// Update: gather winner codeword, residual/quant/loss update, emit bf16 pack
// and next-stage r2 inline (XLA-exact order).
// ---------------------------------------------------------------------------
__global__ void scan_update_kernel(const float* __restrict__ cbs, int q,
                                   const float* __restrict__ x,
                                   float* __restrict__ out_idx_f,
                                   float* __restrict__ out_quant, int is_last)
{
    int wid = threadIdx.x >> 5, lane = threadIdx.x & 31;
    int token = blockIdx.x * 8 + wid;
    const uint4* sc4 = (const uint4*)(g_scores + (size_t)token * Kn);
    const float* cb = cbs + (size_t)q * Kn * Dn;

    // load 1024 fp16 scores: 4 rounds x 8 halves/lane
    float v[32];
    float mn = FLT_MAX;
    #pragma unroll
    for (int r = 0; r < 4; r++) {
        uint4 u = sc4[r * 32 + lane];
        __half2 h[4] = {*(__half2*)&u.x, *(__half2*)&u.y, *(__half2*)&u.z, *(__half2*)&u.w};
        #pragma unroll
        for (int p = 0; p < 4; p++) {
            float2 f = __half22float2(h[p]);
            v[r * 8 + p * 2]     = f.x;
            v[r * 8 + p * 2 + 1] = f.y;
            mn = fminf(mn, fminf(f.x, f.y));
        }
    }
    #pragma unroll
    for (int off = 16; off; off >>= 1)
        mn = fminf(mn, __shfl_xor_sync(0xffffffffu, mn, off));
    float thr = mn + WWIN;

    __shared__ int cnts[8];
    __shared__ int lists[8][CANDCAP];
    if (lane == 0) cnts[wid] = 0;
    __syncwarp();
    #pragma unroll
    for (int r = 0; r < 4; r++) {
        #pragma unroll
        for (int c = 0; c < 8; c++) {
            if (v[r * 8 + c] <= thr) {
                int p = atomicAdd(&cnts[wid], 1);
                if (p < CANDCAP) lists[wid][p] = (r * 32 + lane) * 8 + c;
            }
        }
    }
    __syncwarp();
    int cnt = cnts[wid];
    int winner;

    if (cnt == 1) {
        winner = lists[wid][0];
    } else {
        const float* rrow = g_residual + (size_t)token * Dn;
        float r2 = g_r2[token];
        float bv = FLT_MAX; int bi = 0x7fffffff;
        if (cnt <= CANDCAP) {
            if (lane < cnt) {
                int k = lists[wid][lane];
                const float* cr = cb + (size_t)k * Dn;
                float acc = 0.f;
                #pragma unroll 8
                for (int d = 0; d < Dn; d++) acc = __fmaf_rn(rrow[d], cr[d], acc);
                bv = __fadd_rn(__fsub_rn(r2, __fmul_rn(2.f, acc)), g_c2[q * Kn + k]);
                bi = k;
            }
        } else {
            for (int k = lane; k < Kn; k += 32) {
                const float* cr = cb + (size_t)k * Dn;
                float acc = 0.f;
                #pragma unroll 8
                for (int d = 0; d < Dn; d++) acc = __fmaf_rn(rrow[d], cr[d], acc);
                float s = __fadd_rn(__fsub_rn(r2, __fmul_rn(2.f, acc)), g_c2[q * Kn + k]);
                if (s < bv || (s == bv && k < bi)) { bv = s; bi = k; }
            }
        }
        #pragma unroll
        for (int off = 16; off; off >>= 1) {
            float ov = __shfl_xor_sync(0xffffffffu, bv, off);
            int   oi = __shfl_xor_sync(0xffffffffu, bi, off);
            if (ov < bv || (ov == bv && oi < bi)) { bv = ov; bi = oi; }
        }
        winner = bi;
    }

    // ---- update (bit-exact round-3 arithmetic; r2 in XLA-exact order) ----
    const float* cbrow = cb + (size_t)winner * Dn;
    size_t base = (size_t)token * Dn;
    float s = 0.f;
    #pragma unroll
    for (int j = 0; j < 8; j++) {
        int d = lane + 32 * j;
        float qv = cbrow[d];
        float r  = __fsub_rn(g_residual[base + d], qv);
        g_residual[base + d] = r;
        if (!is_last) g_Apack[base + d] = __float2bfloat16_rn(r);
        float quant = (q == 0) ? qv : __fadd_rn(g_quant[base + d], qv);
        g_quant[base + d] = quant;
        if (is_last)
            out_quant[base + d] = __fadd_rn(x[base + d], __fsub_rn(quant, x[base + d]));
        s = __fadd_rn(s, __fmul_rn(r, r));
    }
    #pragma unroll
    for (int off = 16; off; off >>= 1)
        s = __fadd_rn(s, __shfl_down_sync(0xffffffffu, s, off));
    if (lane == 0) {
        if (!is_last) g_r2[token] = s;
        atomicAdd(&g_losspart[token & (LOSS_SLOTS - 1)], (double)s);
        out_idx_f[(size_t)q * Mn + token] = (float)winner;
    }
}

__global__ void finalize_kernel(float* __restrict__ out_loss)
{
    __shared__ double red[256];
    double s = 0.0;
    for (int i = threadIdx.x; i < LOSS_SLOTS; i += 256) s += g_losspart[i];
    red[threadIdx.x] = s;
    __syncthreads();
    #pragma unroll
    for (int st = 128; st > 0; st >>= 1) {
        if (threadIdx.x < st) red[threadIdx.x] += red[threadIdx.x + st];
        __syncthreads();
    }
    if (threadIdx.x == 0) {
        float v = (float)(1.25 * red[0] / (double)((size_t)Mn * Dn));
        #pragma unroll
        for (int q = 0; q < Qn; q++) out_loss[q] = v;
    }
}

// ---------------------------------------------------------------------------
extern "C" void kernel_launch(void* const* d_in, const int* in_sizes, int n_in,
                              void* d_out, int out_size)
{
    const float* x   = (const float*)d_in[0];
    const float* cbs = (const float*)d_in[1];
    if (n_in >= 2 && in_sizes[0] == Qn * Kn * Dn && in_sizes[1] == Mn * Dn) {
        const float* t = x; x = cbs; cbs = t;
    }

    float* out       = (float*)d_out;
    float* out_quant = out;                                       // [B,T,D]
    float* out_idx   = out + (size_t)Mn * Dn;                     // [Q,B,T]
    float* out_loss  = out + (size_t)Mn * Dn + (size_t)Qn * Mn;   // 4 scalars
    (void)out_size;

    cudaFuncSetAttribute(gemm_kernel,
                         cudaFuncAttributeMaxDynamicSharedMemorySize, SM_TOT);

    prep0_kernel<<<Mn / 8, 256>>>(x);
    c2_kernel<<<(Qn * Kn * 32) / 256, 256>>>(cbs);
    packB_kernel<<<(Qn * Kn * Dn / 4) / 256, 256>>>(cbs);

    for (int q = 0; q < Qn; q++) {
        gemm_kernel<<<Mn / 128, 256, SM_TOT>>>(q);
        scan_update_kernel<<<Mn / 8, 256>>>(cbs, q, x, out_idx, out_quant,
                                            (q == Qn - 1) ? 1 : 0);
    }

    finalize_kernel<<<1, 256>>>(out_loss);
}

// round 7
// speedup vs baseline: 3.4422x; 1.1553x over previous
#include <cuda_runtime.h>
#include <cuda_bf16.h>
#include <cuda_fp16.h>
#include <cfloat>
#include <cstddef>
#include <cstdint>

// Problem constants (fixed by the reference)
#define Bn 16
#define Tn 2048
#define Dn 256
#define Qn 4
#define Kn 1024
#define Mn (Bn*Tn)          // 32768 tokens

#define LOSS_SLOTS 1024
#define WWIN  4.0f           // candidate window: 2x(bf16 gemm err) + fp16 ulp slack
#define CANDCAP 32

// ------------------------- device global scratch ---------------------------
__device__ __align__(16) float          g_residual[Mn*Dn];
__device__ __align__(16) float          g_c2[Qn*Kn];
__device__ __align__(16) float          g_r2[Mn];
__device__              double          g_losspart[LOSS_SLOTS];
__device__ __align__(16) __nv_bfloat16  g_Apack[(size_t)Mn*Dn];      // bf16(residual)
__device__ __align__(16) __nv_bfloat16  g_Bpack[(size_t)Qn*Kn*Dn];   // bf16(codebooks)
__device__ __align__(16) __half         g_scores[(size_t)Mn*Kn];     // 64 MB approx scores

// ------------------------------ PTX helpers --------------------------------
__device__ __forceinline__ uint32_t smem_to_u32(const void* p) {
    uint32_t a;
    asm("{ .reg .u64 t; cvta.to.shared.u64 t, %1; cvt.u32.u64 %0, t; }"
        : "=r"(a) : "l"(p));
    return a;
}
#define CP_ASYNC16(dst, src) \
    asm volatile("cp.async.cg.shared.global [%0], [%1], 16;" :: "r"(dst), "l"(src))
#define CP_COMMIT() asm volatile("cp.async.commit_group;" ::: "memory")
#define CP_WAIT0()  asm volatile("cp.async.wait_group 0;" ::: "memory")
#define LDSM_X4(r0, r1, r2, r3, addr) \
    asm volatile("ldmatrix.sync.aligned.m8n8.x4.shared.b16 {%0,%1,%2,%3}, [%4];" \
                 : "=r"(r0), "=r"(r1), "=r"(r2), "=r"(r3) : "r"(addr))
#define MMA16816(c, a, b0v, b1v) \
    asm volatile("mma.sync.aligned.m16n8k16.row.col.f32.bf16.bf16.f32 " \
                 "{%0,%1,%2,%3}, {%4,%5,%6,%7}, {%8,%9}, {%0,%1,%2,%3};" \
                 : "+f"((c)[0]), "+f"((c)[1]), "+f"((c)[2]), "+f"((c)[3]) \
                 : "r"((a)[0]), "r"((a)[1]), "r"((a)[2]), "r"((a)[3]), \
                   "r"(b0v), "r"(b1v))

// XLA-mimicking warp row-norm: separate rounded multiply + add (NO FMA),
// lane-strided ascending, then shfl_down tree 16..1.  (bit-exact, round 3)
__device__ __forceinline__ float warp_rownorm(const float* __restrict__ row, int lane) {
    float s = 0.f;
    #pragma unroll
    for (int d = lane; d < Dn; d += 32) {
        float v = row[d];
        s = __fadd_rn(s, __fmul_rn(v, v));
    }
    #pragma unroll
    for (int off = 16; off; off >>= 1)
        s = __fadd_rn(s, __shfl_down_sync(0xffffffffu, s, off));
    return s;
}

// ---------------------------------------------------------------------------
// prep0: residual = x, bf16 pack, r2 (XLA-exact order), zero loss slots.
// ---------------------------------------------------------------------------
__global__ void prep0_kernel(const float* __restrict__ x) {
    int wid = threadIdx.x >> 5, lane = threadIdx.x & 31;
    int token = blockIdx.x * 8 + wid;
    size_t base = (size_t)token * Dn;
    float s = 0.f;
    #pragma unroll
    for (int j = 0; j < 8; j++) {
        int d = lane + 32 * j;
        float v = x[base + d];
        g_residual[base + d] = v;
        g_Apack[base + d] = __float2bfloat16_rn(v);
        s = __fadd_rn(s, __fmul_rn(v, v));
    }
    #pragma unroll
    for (int off = 16; off; off >>= 1)
        s = __fadd_rn(s, __shfl_down_sync(0xffffffffu, s, off));
    if (lane == 0) g_r2[token] = s;
    if (blockIdx.x == 0) {
        for (int i = threadIdx.x; i < LOSS_SLOTS; i += 256) g_losspart[i] = 0.0;
    }
}

__global__ void c2_kernel(const float* __restrict__ cbs) {
    int w    = (blockIdx.x * blockDim.x + threadIdx.x) >> 5;
    int lane = threadIdx.x & 31;
    if (w >= Qn * Kn) return;
    float s = warp_rownorm(cbs + (size_t)w * Dn, lane);
    if (lane == 0) g_c2[w] = s;
}

// codebooks -> bf16 (once)
__global__ void packB_kernel(const float* __restrict__ cbs) {
    int i = (blockIdx.x * blockDim.x + threadIdx.x) * 4;
    float4 v = *(const float4*)(cbs + i);
    __nv_bfloat162* dst = (__nv_bfloat162*)(g_Bpack + i);
    dst[0] = __floats2bfloat162_rn(v.x, v.y);
    dst[1] = __floats2bfloat162_rn(v.z, v.w);
}

// ---------------------------------------------------------------------------
// bf16 HMMA GEMM: 128 tokens/CTA x 1024 codes, K=256.
// A resident in SMEM (64 KB, loaded once); B streamed as 32 chunks of 16 KB
// through a double buffer with one cp.async group in flight.
// Writes approx scores s = fl(fl(r2 - 2*dot) + c2) as fp16 to g_scores.
// ---------------------------------------------------------------------------
#define SM_A  0                      // 4 chunks x 16384 = 65536
#define SM_B0 65536
#define SM_B1 (65536 + 16384)
#define SM_C2 (65536 + 32768)
#define SM_TOT (65536 + 32768 + 4096)

__global__ void __launch_bounds__(256, 2)
gemm_kernel(int q)
{
    extern __shared__ char smem[];
    uint32_t sb = smem_to_u32(smem);
    float* c2s = (float*)(smem + SM_C2);

    int tid = threadIdx.x, lane = tid & 31, wid = tid >> 5;
    int wm = wid >> 1, wn = wid & 1;
    int rowBase = blockIdx.x * 128;

    for (int i = tid; i < Kn; i += 256) c2s[i] = g_c2[q * Kn + i];

    float r2a[2][2];
    #pragma unroll
    for (int mf = 0; mf < 2; mf++)
        #pragma unroll
        for (int h = 0; h < 2; h++)
            r2a[mf][h] = g_r2[rowBase + wm * 32 + mf * 16 + (lane >> 2) + h * 8];

    const __nv_bfloat16* baseB = g_Bpack + (size_t)q * Kn * Dn;

    // A -> SMEM once: 16 x 16B per thread, chunked layout [cc][row][64k]
    #pragma unroll
    for (int j = 0; j < 16; j++) {
        int linear = tid + 256 * j;
        int row = linear >> 5;          // 0..127
        int m8  = linear & 31;          // 16B chunk within row
        int cc  = m8 >> 3, m8c = m8 & 7;
        uint32_t sw = (uint32_t)((m8c ^ (row & 7)) << 4);
        CP_ASYNC16(sb + SM_A + cc * 16384 + row * 128 + sw,
                   g_Apack + (size_t)(rowBase + row) * Dn + m8 * 8);
    }
    CP_COMMIT();

    // B chunk 0
    #pragma unroll
    for (int j = 0; j < 4; j++) {
        int linear = tid + 256 * j;
        int row = linear >> 3, m8 = linear & 7;
        uint32_t sw = (uint32_t)((m8 ^ (row & 7)) << 4);
        CP_ASYNC16(sb + SM_B0 + row * 128 + sw,
                   baseB + (size_t)row * Dn + m8 * 8);
    }
    CP_COMMIT();

    float acc[2][8][4];
    #pragma unroll
    for (int a = 0; a < 2; a++)
        #pragma unroll
        for (int b = 0; b < 8; b++)
            #pragma unroll
            for (int c = 0; c < 4; c++) acc[a][b][c] = 0.f;

    for (int bc = 0; bc < 32; bc++) {
        int nt = bc >> 2, cc = bc & 3;
        CP_WAIT0();
        __syncthreads();

        if (bc < 31) {
            int nbc = bc + 1;
            int nnt = nbc >> 2, ncc = nbc & 3;
            uint32_t buf = (nbc & 1) ? SM_B1 : SM_B0;
            int koff = ncc * 64;
            #pragma unroll
            for (int j = 0; j < 4; j++) {
                int linear = tid + 256 * j;
                int row = linear >> 3, m8 = linear & 7;
                uint32_t sw = (uint32_t)((m8 ^ (row & 7)) << 4);
                CP_ASYNC16(sb + buf + row * 128 + sw,
                           baseB + (size_t)(nnt * 128 + row) * Dn + koff + m8 * 8);
            }
            CP_COMMIT();
        }

        uint32_t abase = sb + SM_A + cc * 16384;
        uint32_t bbase = sb + ((bc & 1) ? SM_B1 : SM_B0);

        #pragma unroll
        for (int ks = 0; ks < 4; ks++) {
            uint32_t afr[2][4];
            #pragma unroll
            for (int mf = 0; mf < 2; mf++) {
                int t = lane >> 3;
                int row = wm * 32 + mf * 16 + (lane & 7) + ((t & 1) << 3);
                int kk  = ks * 16 + ((t >> 1) << 3);
                uint32_t addr = abase + row * 128 + ((((kk >> 3) ^ (row & 7)) << 4));
                LDSM_X4(afr[mf][0], afr[mf][1], afr[mf][2], afr[mf][3], addr);
            }
            #pragma unroll
            for (int nf2 = 0; nf2 < 4; nf2++) {
                uint32_t b0, b1, b2, b3;
                int t = lane >> 3;
                int row = wn * 64 + nf2 * 16 + ((t >> 1) << 3) + (lane & 7);
                int kk  = ks * 16 + ((t & 1) << 3);
                uint32_t addr = bbase + row * 128 + ((((kk >> 3) ^ (row & 7)) << 4));
                LDSM_X4(b0, b1, b2, b3, addr);
                MMA16816(acc[0][nf2 * 2],     afr[0], b0, b1);
                MMA16816(acc[0][nf2 * 2 + 1], afr[0], b2, b3);
                MMA16816(acc[1][nf2 * 2],     afr[1], b0, b1);
                MMA16816(acc[1][nf2 * 2 + 1], afr[1], b2, b3);
            }
        }

        if (cc == 3) {
            // ---- epilogue tile nt: fp16 approx scores to global ----
            #pragma unroll
            for (int mf = 0; mf < 2; mf++) {
                int ra = rowBase + wm * 32 + mf * 16 + (lane >> 2);
                #pragma unroll
                for (int nf = 0; nf < 8; nf++) {
                    int col = nt * 128 + wn * 64 + nf * 8 + (lane & 3) * 2;
                    float cA = c2s[col], cB = c2s[col + 1];
                    float s0x = __fadd_rn(__fsub_rn(r2a[mf][0], __fmul_rn(2.f, acc[mf][nf][0])), cA);
                    float s0y = __fadd_rn(__fsub_rn(r2a[mf][0], __fmul_rn(2.f, acc[mf][nf][1])), cB);
                    float s1x = __fadd_rn(__fsub_rn(r2a[mf][1], __fmul_rn(2.f, acc[mf][nf][2])), cA);
                    float s1y = __fadd_rn(__fsub_rn(r2a[mf][1], __fmul_rn(2.f, acc[mf][nf][3])), cB);
                    *(__half2*)(g_scores + (size_t)ra * Kn + col)       = __floats2half2_rn(s0x, s0y);
                    *(__half2*)(g_scores + (size_t)(ra + 8) * Kn + col) = __floats2half2_rn(s1x, s1y);
                }
            }
            #pragma unroll
            for (int a = 0; a < 2; a++)
                #pragma unroll
                for (int b = 0; b < 8; b++)
                    #pragma unroll
                    for (int c = 0; c < 4; c++) acc[a][b][c] = 0.f;
        }
    }
}

// ---------------------------------------------------------------------------
// Fused scan + update. One warp per token, 8 tokens per block.
// Scan: approx min over fp16 scores, candidates within WWIN, exact-evaluate
// with the reference-faithful chain (round-3 bit-exact).
// Update: gather winner, residual/loss update, bf16 pack + next r2 inline.
// Output quant = fl(x - r_final)  (== x + (quant-x) to ~2 ulp; sub-1e-6 rel).
// ---------------------------------------------------------------------------
__global__ void scan_update_kernel(const float* __restrict__ cbs, int q,
                                   const float* __restrict__ x,
                                   float* __restrict__ out_idx_f,
                                   float* __restrict__ out_quant, int is_last)
{
    int wid = threadIdx.x >> 5, lane = threadIdx.x & 31;
    int token = blockIdx.x * 8 + wid;
    const uint4* sc4 = (const uint4*)(g_scores + (size_t)token * Kn);
    const float* cb = cbs + (size_t)q * Kn * Dn;

    float v[32];
    float mn = FLT_MAX;
    #pragma unroll
    for (int r = 0; r < 4; r++) {
        uint4 u = sc4[r * 32 + lane];
        __half2 h[4] = {*(__half2*)&u.x, *(__half2*)&u.y, *(__half2*)&u.z, *(__half2*)&u.w};
        #pragma unroll
        for (int p = 0; p < 4; p++) {
            float2 f = __half22float2(h[p]);
            v[r * 8 + p * 2]     = f.x;
            v[r * 8 + p * 2 + 1] = f.y;
            mn = fminf(mn, fminf(f.x, f.y));
        }
    }
    #pragma unroll
    for (int off = 16; off; off >>= 1)
        mn = fminf(mn, __shfl_xor_sync(0xffffffffu, mn, off));
    float thr = mn + WWIN;

    __shared__ int cnts[8];
    __shared__ int lists[8][CANDCAP];
    if (lane == 0) cnts[wid] = 0;
    __syncwarp();
    #pragma unroll
    for (int r = 0; r < 4; r++) {
        #pragma unroll
        for (int c = 0; c < 8; c++) {
            if (v[r * 8 + c] <= thr) {
                int p = atomicAdd(&cnts[wid], 1);
                if (p < CANDCAP) lists[wid][p] = (r * 32 + lane) * 8 + c;
            }
        }
    }
    __syncwarp();
    int cnt = cnts[wid];
    int winner;

    if (cnt == 1) {
        winner = lists[wid][0];
    } else {
        const float* rrow = g_residual + (size_t)token * Dn;
        float r2 = g_r2[token];
        float bv = FLT_MAX; int bi = 0x7fffffff;
        if (cnt <= CANDCAP) {
            if (lane < cnt) {
                int k = lists[wid][lane];
                const float* cr = cb + (size_t)k * Dn;
                float acc = 0.f;
                #pragma unroll 8
                for (int d = 0; d < Dn; d++) acc = __fmaf_rn(rrow[d], cr[d], acc);
                bv = __fadd_rn(__fsub_rn(r2, __fmul_rn(2.f, acc)), g_c2[q * Kn + k]);
                bi = k;
            }
        } else {
            for (int k = lane; k < Kn; k += 32) {
                const float* cr = cb + (size_t)k * Dn;
                float acc = 0.f;
                #pragma unroll 8
                for (int d = 0; d < Dn; d++) acc = __fmaf_rn(rrow[d], cr[d], acc);
                float s = __fadd_rn(__fsub_rn(r2, __fmul_rn(2.f, acc)), g_c2[q * Kn + k]);
                if (s < bv || (s == bv && k < bi)) { bv = s; bi = k; }
            }
        }
        #pragma unroll
        for (int off = 16; off; off >>= 1) {
            float ov = __shfl_xor_sync(0xffffffffu, bv, off);
            int   oi = __shfl_xor_sync(0xffffffffu, bi, off);
            if (ov < bv || (ov == bv && oi < bi)) { bv = ov; bi = oi; }
        }
        winner = bi;
    }

    // ---- update (bit-exact residual chain; r2 in XLA-exact order) ----
    const float* cbrow = cb + (size_t)winner * Dn;
    size_t base = (size_t)token * Dn;
    float s = 0.f;
    #pragma unroll
    for (int j = 0; j < 8; j++) {
        int d = lane + 32 * j;
        float qv = cbrow[d];
        float r  = __fsub_rn(g_residual[base + d], qv);
        g_residual[base + d] = r;
        if (!is_last) g_Apack[base + d] = __float2bfloat16_rn(r);
        else          out_quant[base + d] = __fsub_rn(x[base + d], r);
        s = __fadd_rn(s, __fmul_rn(r, r));
    }
    #pragma unroll
    for (int off = 16; off; off >>= 1)
        s = __fadd_rn(s, __shfl_down_sync(0xffffffffu, s, off));
    if (lane == 0) {
        if (!is_last) g_r2[token] = s;
        atomicAdd(&g_losspart[token & (LOSS_SLOTS - 1)], (double)s);
        out_idx_f[(size_t)q * Mn + token] = (float)winner;
    }
}

__global__ void finalize_kernel(float* __restrict__ out_loss)
{
    __shared__ double red[256];
    double s = 0.0;
    for (int i = threadIdx.x; i < LOSS_SLOTS; i += 256) s += g_losspart[i];
    red[threadIdx.x] = s;
    __syncthreads();
    #pragma unroll
    for (int st = 128; st > 0; st >>= 1) {
        if (threadIdx.x < st) red[threadIdx.x] += red[threadIdx.x + st];
        __syncthreads();
    }
    if (threadIdx.x == 0) {
        float v = (float)(1.25 * red[0] / (double)((size_t)Mn * Dn));
        #pragma unroll
        for (int q = 0; q < Qn; q++) out_loss[q] = v;
    }
}

// ---------------------------------------------------------------------------
extern "C" void kernel_launch(void* const* d_in, const int* in_sizes, int n_in,
                              void* d_out, int out_size)
{
    const float* x   = (const float*)d_in[0];
    const float* cbs = (const float*)d_in[1];
    if (n_in >= 2 && in_sizes[0] == Qn * Kn * Dn && in_sizes[1] == Mn * Dn) {
        const float* t = x; x = cbs; cbs = t;
    }

    float* out       = (float*)d_out;
    float* out_quant = out;                                       // [B,T,D]
    float* out_idx   = out + (size_t)Mn * Dn;                     // [Q,B,T]
    float* out_loss  = out + (size_t)Mn * Dn + (size_t)Qn * Mn;   // 4 scalars
    (void)out_size;

    cudaFuncSetAttribute(gemm_kernel,
                         cudaFuncAttributeMaxDynamicSharedMemorySize, SM_TOT);

    prep0_kernel<<<Mn / 8, 256>>>(x);
    c2_kernel<<<(Qn * Kn * 32) / 256, 256>>>(cbs);
    packB_kernel<<<(Qn * Kn * Dn / 4) / 256, 256>>>(cbs);

    for (int q = 0; q < Qn; q++) {
        gemm_kernel<<<Mn / 128, 256, SM_TOT>>>(q);
        scan_update_kernel<<<Mn / 8, 256>>>(cbs, q, x, out_idx, out_quant,
                                            (q == Qn - 1) ? 1 : 0);
    }

    finalize_kernel<<<1, 256>>>(out_loss);
}

// round 9
// speedup vs baseline: 3.9109x; 1.1361x over previous
#include <cuda_runtime.h>
#include <cuda_bf16.h>
#include <cuda_fp16.h>
#include <cfloat>
#include <cstddef>
#include <cstdint>

// Problem constants (fixed by the reference)
#define Bn 16
#define Tn 2048
#define Dn 256
#define Qn 4
#define Kn 1024
#define Mn (Bn*Tn)          // 32768 tokens

#define LOSS_SLOTS 1024
#define WWIN  4.0f           // candidate window: 2*(bf16 gemm err) + fp16 ulp slack
#define CANDCAP 32

// ------------------------- device global scratch ---------------------------
__device__ __align__(16) float          g_residual[Mn*Dn];
__device__ __align__(16) float          g_c2[Qn*Kn];
__device__ __align__(16) float          g_r2[Mn];
__device__              double          g_losspart[LOSS_SLOTS];
__device__ __align__(16) __nv_bfloat16  g_Apack[(size_t)Mn*Dn];      // bf16(residual)
__device__ __align__(16) __nv_bfloat16  g_Bpack[(size_t)Qn*Kn*Dn];   // bf16(codebooks)
__device__ __align__(16) __half         g_scores[(size_t)Mn*Kn];     // 64 MB approx scores
__device__ __align__(16) float          g_hmin[(size_t)Mn*16];       // per-64-code-half mins

// ------------------------------ PTX helpers --------------------------------
__device__ __forceinline__ uint32_t smem_to_u32(const void* p) {
    uint32_t a;
    asm("{ .reg .u64 t; cvta.to.shared.u64 t, %1; cvt.u32.u64 %0, t; }"
        : "=r"(a) : "l"(p));
    return a;
}
#define CP_ASYNC16(dst, src) \
    asm volatile("cp.async.cg.shared.global [%0], [%1], 16;" :: "r"(dst), "l"(src))
#define CP_COMMIT() asm volatile("cp.async.commit_group;" ::: "memory")
#define CP_WAIT0()  asm volatile("cp.async.wait_group 0;" ::: "memory")
#define LDSM_X4(r0, r1, r2, r3, addr) \
    asm volatile("ldmatrix.sync.aligned.m8n8.x4.shared.b16 {%0,%1,%2,%3}, [%4];" \
                 : "=r"(r0), "=r"(r1), "=r"(r2), "=r"(r3) : "r"(addr))
#define MMA16816(c, a, b0v, b1v) \
    asm volatile("mma.sync.aligned.m16n8k16.row.col.f32.bf16.bf16.f32 " \
                 "{%0,%1,%2,%3}, {%4,%5,%6,%7}, {%8,%9}, {%0,%1,%2,%3};" \
                 : "+f"((c)[0]), "+f"((c)[1]), "+f"((c)[2]), "+f"((c)[3]) \
                 : "r"((a)[0]), "r"((a)[1]), "r"((a)[2]), "r"((a)[3]), \
                   "r"(b0v), "r"(b1v))

// ---------------------------------------------------------------------------
// prep0: residual = x, bf16 pack, r2 (XLA-exact order), zero loss slots.
// ---------------------------------------------------------------------------
__global__ void prep0_kernel(const float* __restrict__ x) {
    int wid = threadIdx.x >> 5, lane = threadIdx.x & 31;
    int token = blockIdx.x * 8 + wid;
    size_t base = (size_t)token * Dn;
    float s = 0.f;
    #pragma unroll
    for (int j = 0; j < 8; j++) {
        int d = lane + 32 * j;
        float v = x[base + d];
        g_residual[base + d] = v;
        g_Apack[base + d] = __float2bfloat16_rn(v);
        s = __fadd_rn(s, __fmul_rn(v, v));
    }
    #pragma unroll
    for (int off = 16; off; off >>= 1)
        s = __fadd_rn(s, __shfl_down_sync(0xffffffffu, s, off));
    if (lane == 0) g_r2[token] = s;
    if (blockIdx.x == 0) {
        for (int i = threadIdx.x; i < LOSS_SLOTS; i += 256) g_losspart[i] = 0.0;
    }
}

// codebooks -> bf16 pack + c2 (XLA-exact order), one warp per codeword
__global__ void packBc2_kernel(const float* __restrict__ cbs) {
    int w    = (blockIdx.x * blockDim.x + threadIdx.x) >> 5;
    int lane = threadIdx.x & 31;
    if (w >= Qn * Kn) return;
    const float* row = cbs + (size_t)w * Dn;
    float s = 0.f;
    #pragma unroll
    for (int j = 0; j < 8; j++) {
        int d = lane + 32 * j;
        float v = row[d];
        g_Bpack[(size_t)w * Dn + d] = __float2bfloat16_rn(v);
        s = __fadd_rn(s, __fmul_rn(v, v));
    }
    #pragma unroll
    for (int off = 16; off; off >>= 1)
        s = __fadd_rn(s, __shfl_down_sync(0xffffffffu, s, off));
    if (lane == 0) g_c2[w] = s;
}

// ---------------------------------------------------------------------------
// bf16 HMMA GEMM: 128 tokens/CTA x 1024 codes, K=256. A resident in SMEM,
// B double-buffered. Epilogue: fp16 scores + per-(row, 64-code-half) fp32 min.
// ---------------------------------------------------------------------------
#define SM_A  0                      // 4 chunks x 16384 = 65536
#define SM_B0 65536
#define SM_B1 (65536 + 16384)
#define SM_C2 (65536 + 32768)
#define SM_TOT (65536 + 32768 + 4096)

__global__ void __launch_bounds__(256, 2)
gemm_kernel(int q)
{
    extern __shared__ char smem[];
    uint32_t sb = smem_to_u32(smem);
    float* c2s = (float*)(smem + SM_C2);

    int tid = threadIdx.x, lane = tid & 31, wid = tid >> 5;
    int wm = wid >> 1, wn = wid & 1;
    int rowBase = blockIdx.x * 128;

    for (int i = tid; i < Kn; i += 256) c2s[i] = g_c2[q * Kn + i];

    float r2a[2][2];
    #pragma unroll
    for (int mf = 0; mf < 2; mf++)
        #pragma unroll
        for (int h = 0; h < 2; h++)
            r2a[mf][h] = g_r2[rowBase + wm * 32 + mf * 16 + (lane >> 2) + h * 8];

    const __nv_bfloat16* baseB = g_Bpack + (size_t)q * Kn * Dn;

    // A -> SMEM once: chunked layout [cc][row][64k]
    #pragma unroll
    for (int j = 0; j < 16; j++) {
        int linear = tid + 256 * j;
        int row = linear >> 5;
        int m8  = linear & 31;
        int cc  = m8 >> 3, m8c = m8 & 7;
        uint32_t sw = (uint32_t)((m8c ^ (row & 7)) << 4);
        CP_ASYNC16(sb + SM_A + cc * 16384 + row * 128 + sw,
                   g_Apack + (size_t)(rowBase + row) * Dn + m8 * 8);
    }
    CP_COMMIT();

    // B chunk 0
    #pragma unroll
    for (int j = 0; j < 4; j++) {
        int linear = tid + 256 * j;
        int row = linear >> 3, m8 = linear & 7;
        uint32_t sw = (uint32_t)((m8 ^ (row & 7)) << 4);
        CP_ASYNC16(sb + SM_B0 + row * 128 + sw,
                   baseB + (size_t)row * Dn + m8 * 8);
    }
    CP_COMMIT();

    float acc[2][8][4];
    #pragma unroll
    for (int a = 0; a < 2; a++)
        #pragma unroll
        for (int b = 0; b < 8; b++)
            #pragma unroll
            for (int c = 0; c < 4; c++) acc[a][b][c] = 0.f;

    for (int bc = 0; bc < 32; bc++) {
        int nt = bc >> 2, cc = bc & 3;
        CP_WAIT0();
        __syncthreads();

        if (bc < 31) {
            int nbc = bc + 1;
            int nnt = nbc >> 2, ncc = nbc & 3;
            uint32_t buf = (nbc & 1) ? SM_B1 : SM_B0;
            int koff = ncc * 64;
            #pragma unroll
            for (int j = 0; j < 4; j++) {
                int linear = tid + 256 * j;
                int row = linear >> 3, m8 = linear & 7;
                uint32_t sw = (uint32_t)((m8 ^ (row & 7)) << 4);
                CP_ASYNC16(sb + buf + row * 128 + sw,
                           baseB + (size_t)(nnt * 128 + row) * Dn + koff + m8 * 8);
            }
            CP_COMMIT();
        }

        uint32_t abase = sb + SM_A + cc * 16384;
        uint32_t bbase = sb + ((bc & 1) ? SM_B1 : SM_B0);

        #pragma unroll
        for (int ks = 0; ks < 4; ks++) {
            uint32_t afr[2][4];
            #pragma unroll
            for (int mf = 0; mf < 2; mf++) {
                int t = lane >> 3;
                int row = wm * 32 + mf * 16 + (lane & 7) + ((t & 1) << 3);
                int kk  = ks * 16 + ((t >> 1) << 3);
                uint32_t addr = abase + row * 128 + ((((kk >> 3) ^ (row & 7)) << 4));
                LDSM_X4(afr[mf][0], afr[mf][1], afr[mf][2], afr[mf][3], addr);
            }
            #pragma unroll
            for (int nf2 = 0; nf2 < 4; nf2++) {
                uint32_t b0, b1, b2, b3;
                int t = lane >> 3;
                int row = wn * 64 + nf2 * 16 + ((t >> 1) << 3) + (lane & 7);
                int kk  = ks * 16 + ((t & 1) << 3);
                uint32_t addr = bbase + row * 128 + ((((kk >> 3) ^ (row & 7)) << 4));
                LDSM_X4(b0, b1, b2, b3, addr);
                MMA16816(acc[0][nf2 * 2],     afr[0], b0, b1);
                MMA16816(acc[0][nf2 * 2 + 1], afr[0], b2, b3);
                MMA16816(acc[1][nf2 * 2],     afr[1], b0, b1);
                MMA16816(acc[1][nf2 * 2 + 1], afr[1], b2, b3);
            }
        }

        if (cc == 3) {
            // ---- epilogue tile nt: fp16 scores + half-tile mins ----
            #pragma unroll
            for (int mf = 0; mf < 2; mf++) {
                int ra = rowBase + wm * 32 + mf * 16 + (lane >> 2);
                float lmin0 = FLT_MAX, lmin1 = FLT_MAX;
                #pragma unroll
                for (int nf = 0; nf < 8; nf++) {
                    int col = nt * 128 + wn * 64 + nf * 8 + (lane & 3) * 2;
                    float cA = c2s[col], cB = c2s[col + 1];
                    float s0x = __fadd_rn(__fsub_rn(r2a[mf][0], __fmul_rn(2.f, acc[mf][nf][0])), cA);
                    float s0y = __fadd_rn(__fsub_rn(r2a[mf][0], __fmul_rn(2.f, acc[mf][nf][1])), cB);
                    float s1x = __fadd_rn(__fsub_rn(r2a[mf][1], __fmul_rn(2.f, acc[mf][nf][2])), cA);
                    float s1y = __fadd_rn(__fsub_rn(r2a[mf][1], __fmul_rn(2.f, acc[mf][nf][3])), cB);
                    lmin0 = fminf(lmin0, fminf(s0x, s0y));
                    lmin1 = fminf(lmin1, fminf(s1x, s1y));
                    *(__half2*)(g_scores + (size_t)ra * Kn + col)       = __floats2half2_rn(s0x, s0y);
                    *(__half2*)(g_scores + (size_t)(ra + 8) * Kn + col) = __floats2half2_rn(s1x, s1y);
                }
                // quad-reduce (lanes sharing a row) and store half-tile mins
                lmin0 = fminf(lmin0, __shfl_xor_sync(0xffffffffu, lmin0, 1));
                lmin0 = fminf(lmin0, __shfl_xor_sync(0xffffffffu, lmin0, 2));
                lmin1 = fminf(lmin1, __shfl_xor_sync(0xffffffffu, lmin1, 1));
                lmin1 = fminf(lmin1, __shfl_xor_sync(0xffffffffu, lmin1, 2));
                if ((lane & 3) == 0) {
                    g_hmin[(size_t)ra * 16 + nt * 2 + wn]       = lmin0;
                    g_hmin[(size_t)(ra + 8) * 16 + nt * 2 + wn] = lmin1;
                }
            }
            #pragma unroll
            for (int a = 0; a < 2; a++)
                #pragma unroll
                for (int b = 0; b < 8; b++)
                    #pragma unroll
                    for (int c = 0; c < 4; c++) acc[a][b][c] = 0.f;
        }
    }
}

// ---------------------------------------------------------------------------
// Fused scan + update with half-tile pruning. One warp per token.
// Reads 16 half-mins; only half-tiles with min <= thr+0.5 have their fp16
// scores fetched. Candidates within WWIN exact-rechecked (round-3 bit-exact).
// ---------------------------------------------------------------------------
__global__ void scan_update_kernel(const float* __restrict__ cbs, int q,
                                   const float* __restrict__ x,
                                   float* __restrict__ out_idx_f,
                                   float* __restrict__ out_quant, int is_last)
{
    int wid = threadIdx.x >> 5, lane = threadIdx.x & 31;
    int token = blockIdx.x * 8 + wid;
    const float* cb = cbs + (size_t)q * Kn * Dn;

    // half-tile mins (fp32, exact mins of pre-rounding scores)
    float hm = (lane < 16) ? g_hmin[(size_t)token * 16 + lane] : FLT_MAX;
    float mn = hm;
    #pragma unroll
    for (int off = 16; off; off >>= 1)
        mn = fminf(mn, __shfl_xor_sync(0xffffffffu, mn, off));
    float thr  = mn + WWIN;
    float thrt = thr + 0.5f;        // fp16-ulp guard for pruning

    __shared__ int cnts[8];
    __shared__ int lists[8][CANDCAP];
    if (lane == 0) cnts[wid] = 0;
    __syncwarp();

    const uint32_t* sp = (const uint32_t*)(g_scores + (size_t)token * Kn);
    #pragma unroll 1
    for (int ht = 0; ht < 16; ht++) {
        float hv = __shfl_sync(0xffffffffu, hm, ht);
        if (hv <= thrt) {
            uint32_t u = sp[ht * 32 + lane];
            float2 f = __half22float2(*(__half2*)&u);
            if (f.x <= thr) {
                int p = atomicAdd(&cnts[wid], 1);
                if (p < CANDCAP) lists[wid][p] = ht * 64 + lane * 2;
            }
            if (f.y <= thr) {
                int p = atomicAdd(&cnts[wid], 1);
                if (p < CANDCAP) lists[wid][p] = ht * 64 + lane * 2 + 1;
            }
        }
    }
    __syncwarp();
    int cnt = cnts[wid];
    int winner;

    if (cnt == 1) {
        winner = lists[wid][0];
    } else {
        const float* rrow = g_residual + (size_t)token * Dn;
        float r2 = g_r2[token];
        float bv = FLT_MAX; int bi = 0x7fffffff;
        if (cnt <= CANDCAP) {
            if (lane < cnt) {
                int k = lists[wid][lane];
                const float* cr = cb + (size_t)k * Dn;
                float acc = 0.f;
                #pragma unroll 8
                for (int d = 0; d < Dn; d++) acc = __fmaf_rn(rrow[d], cr[d], acc);
                bv = __fadd_rn(__fsub_rn(r2, __fmul_rn(2.f, acc)), g_c2[q * Kn + k]);
                bi = k;
            }
        } else {
            for (int k = lane; k < Kn; k += 32) {
                const float* cr = cb + (size_t)k * Dn;
                float acc = 0.f;
                #pragma unroll 8
                for (int d = 0; d < Dn; d++) acc = __fmaf_rn(rrow[d], cr[d], acc);
                float s = __fadd_rn(__fsub_rn(r2, __fmul_rn(2.f, acc)), g_c2[q * Kn + k]);
                if (s < bv || (s == bv && k < bi)) { bv = s; bi = k; }
            }
        }
        #pragma unroll
        for (int off = 16; off; off >>= 1) {
            float ov = __shfl_xor_sync(0xffffffffu, bv, off);
            int   oi = __shfl_xor_sync(0xffffffffu, bi, off);
            if (ov < bv || (ov == bv && oi < bi)) { bv = ov; bi = oi; }
        }
        winner = bi;
    }

    // ---- update (bit-exact residual chain; r2 in XLA-exact order) ----
    const float* cbrow = cb + (size_t)winner * Dn;
    size_t base = (size_t)token * Dn;
    float s = 0.f;
    #pragma unroll
    for (int j = 0; j < 8; j++) {
        int d = lane + 32 * j;
        float qv = cbrow[d];
        float r  = __fsub_rn(g_residual[base + d], qv);
        g_residual[base + d] = r;
        if (!is_last) g_Apack[base + d] = __float2bfloat16_rn(r);
        else          out_quant[base + d] = __fsub_rn(x[base + d], r);
        s = __fadd_rn(s, __fmul_rn(r, r));
    }
    #pragma unroll
    for (int off = 16; off; off >>= 1)
        s = __fadd_rn(s, __shfl_down_sync(0xffffffffu, s, off));
    if (lane == 0) {
        if (!is_last) g_r2[token] = s;
        atomicAdd(&g_losspart[token & (LOSS_SLOTS - 1)], (double)s);
        out_idx_f[(size_t)q * Mn + token] = (float)winner;
    }
}

__global__ void finalize_kernel(float* __restrict__ out_loss)
{
    __shared__ double red[256];
    double s = 0.0;
    for (int i = threadIdx.x; i < LOSS_SLOTS; i += 256) s += g_losspart[i];
    red[threadIdx.x] = s;
    __syncthreads();
    #pragma unroll
    for (int st = 128; st > 0; st >>= 1) {
        if (threadIdx.x < st) red[threadIdx.x] += red[threadIdx.x + st];
        __syncthreads();
    }
    if (threadIdx.x == 0) {
        float v = (float)(1.25 * red[0] / (double)((size_t)Mn * Dn));
        #pragma unroll
        for (int q = 0; q < Qn; q++) out_loss[q] = v;
    }
}

// ---------------------------------------------------------------------------
extern "C" void kernel_launch(void* const* d_in, const int* in_sizes, int n_in,
                              void* d_out, int out_size)
{
    const float* x   = (const float*)d_in[0];
    const float* cbs = (const float*)d_in[1];
    if (n_in >= 2 && in_sizes[0] == Qn * Kn * Dn && in_sizes[1] == Mn * Dn) {
        const float* t = x; x = cbs; cbs = t;
    }

    float* out       = (float*)d_out;
    float* out_quant = out;                                       // [B,T,D]
    float* out_idx   = out + (size_t)Mn * Dn;                     // [Q,B,T]
    float* out_loss  = out + (size_t)Mn * Dn + (size_t)Qn * Mn;   // 4 scalars
    (void)out_size;

    cudaFuncSetAttribute(gemm_kernel,
                         cudaFuncAttributeMaxDynamicSharedMemorySize, SM_TOT);

    prep0_kernel<<<Mn / 8, 256>>>(x);
    packBc2_kernel<<<(Qn * Kn * 32) / 256, 256>>>(cbs);

    for (int q = 0; q < Qn; q++) {
        gemm_kernel<<<Mn / 128, 256, SM_TOT>>>(q);
        scan_update_kernel<<<Mn / 8, 256>>>(cbs, q, x, out_idx, out_quant,
                                            (q == Qn - 1) ? 1 : 0);
    }

    finalize_kernel<<<1, 256>>>(out_loss);
}